// round 11
// baseline (speedup 1.0000x reference)
#include <cuda_runtime.h>
#include <cuda_fp16.h>
#include <cstdint>
#include <math.h>

#define KT   16
#define NPER 16384
#define DD   256
#define NTOT (KT * NPER)

#define BK 32
#define NSLICE 8

// smem layout (bytes): 3-stage rings
#define A16_STAGE 10240     // 128 rows x 80B (32 halfs + 8 pad)
#define B16_STAGE 10240
#define A32_STAGE 16384     // 128 rows x 128B, XOR-swizzled
#define A16_OFF   0
#define B16_OFF   (3 * A16_STAGE)               // 30720
#define A32_OFF   (B16_OFF + 3 * B16_STAGE)     // 61440
#define SMEM_BYTES (A32_OFF + 3 * A32_STAGE)    // 110592

// named barriers: full[r] = 1+r (sync both sides), empty[r] = 4+r,
// producer-internal = 7 (64 threads)
#define BAR_SYNC(id)   asm volatile("bar.sync %0, 320;"   :: "r"(id) : "memory")
#define BAR_ARRIVE(id) asm volatile("bar.arrive %0, 320;" :: "r"(id) : "memory")
#define BAR_SYNC_PROD() asm volatile("bar.sync 7, 64;" ::: "memory")

__device__ int    g_inv[NTOT];
__device__ __half g_wh[KT * DD * DD];    // w in fp16

// ---------------------------------------------------------------- prep
__global__ void prep_kernel(const int* __restrict__ perm, const float* __restrict__ w) {
    int i = blockIdx.x * blockDim.x + threadIdx.x;
    if (i < NTOT) g_inv[perm[i]] = i;
    if (i < KT * DD * DD) g_wh[i] = __float2half_rn(w[i]);
}

// ---------------------------------------------------------------- helpers
__device__ __forceinline__ uint32_t smem_u32(const void* p) {
    uint32_t a;
    asm("{ .reg .u64 t; cvta.to.shared.u64 t, %1; cvt.u32.u64 %0, t; }" : "=r"(a) : "l"(p));
    return a;
}
__device__ __forceinline__ void cp16(uint32_t sa, const void* ga) {
    asm volatile("cp.async.cg.shared.global [%0], [%1], 16;" :: "r"(sa), "l"(ga));
}
__device__ __forceinline__ void ldmx4(uint32_t* r, uint32_t addr) {
    asm volatile("ldmatrix.sync.aligned.m8n8.x4.shared.b16 {%0,%1,%2,%3}, [%4];"
                 : "=r"(r[0]), "=r"(r[1]), "=r"(r[2]), "=r"(r[3]) : "r"(addr));
}
__device__ __forceinline__ void mma_f16(float* c, const uint32_t* a, const uint32_t* b) {
    asm volatile(
        "mma.sync.aligned.m16n8k16.row.col.f32.f16.f16.f32 "
        "{%0,%1,%2,%3}, {%4,%5,%6,%7}, {%8,%9}, {%0,%1,%2,%3};"
        : "+f"(c[0]), "+f"(c[1]), "+f"(c[2]), "+f"(c[3])
        : "r"(a[0]), "r"(a[1]), "r"(a[2]), "r"(a[3]), "r"(b[0]), "r"(b[1]));
}
__device__ __forceinline__ float fast_tanh(float v) {
    v = fminf(9.0f, fmaxf(-9.0f, v));
    float e = __expf(2.0f * v);
    return __fdividef(e - 1.0f, e + 1.0f);
}
__device__ __forceinline__ uint32_t h2u(__half2 h) {
    return *reinterpret_cast<uint32_t*>(&h);
}

// producer cp.async for one slice into ring stage (64 threads)
__device__ __forceinline__ void issue_slice(uint32_t sb, const float* xg,
                                            const __half* wh, int s, int stage, int ptid) {
    uint32_t a32 = sb + A32_OFF + stage * A32_STAGE;
    #pragma unroll
    for (int t = 0; t < 16; ++t) {
        int q = ptid + t * 64;          // 0..1023
        int m = q >> 3, j = q & 7;
        cp16(a32 + m * 128 + ((j ^ (m & 7)) << 4), xg + m * DD + s * BK + j * 4);
    }
    uint32_t b16 = sb + B16_OFF + stage * B16_STAGE;
    #pragma unroll
    for (int t = 0; t < 8; ++t) {
        int q = ptid + t * 64;          // 0..511
        int n = q >> 2, c = q & 3;
        cp16(b16 + n * 80 + c * 16, wh + n * DD + s * BK + c * 8);
    }
}

// ---------------------------------------------------------------- main kernel
// 320 threads: warps 0-7 consumers (ldmatrix+mma), warps 8-9 producers
// (cp.async + fp32->fp16 cvt). Named-barrier producer/consumer pipeline.
__global__ __launch_bounds__(320, 2) void gemm_ws_f16(
    const float* __restrict__ x, float* __restrict__ out)
{
    extern __shared__ char smc[];
    const uint32_t sb = smem_u32(smc);

    const int tid  = threadIdx.x;
    const int lane = tid & 31;
    const int wid  = tid >> 5;

    const int half = blockIdx.x;     // 0..1  (N half)
    const int mt   = blockIdx.y;     // 0..127 (M tile)
    const int kz   = blockIdx.z;     // 0..15  (type)

    const float*  xg = x    + (size_t)kz * NPER * DD + (size_t)mt * 128 * DD;
    const __half* wh = g_wh + (size_t)kz * DD * DD   + (size_t)half * 128 * DD;

    if (wid >= 8) {
        // ================= producer =================
        const int ptid = tid - 256;   // 0..63

        issue_slice(sb, xg, wh, 0, 0, ptid);
        asm volatile("cp.async.commit_group;");
        issue_slice(sb, xg, wh, 1, 1, ptid);
        asm volatile("cp.async.commit_group;");

        #pragma unroll 1
        for (int s = 0; s < NSLICE; ++s) {
            const int r = s % 3;
            if (s + 2 < NSLICE) {
                const int rn = (s + 2) % 3;
                if (s + 2 >= 3) BAR_SYNC(4 + rn);       // stage rn freed by consumers
                issue_slice(sb, xg, wh, s + 2, rn, ptid);
                asm volatile("cp.async.commit_group;");
            }
            if (s < 6)       asm volatile("cp.async.wait_group 2;");
            else if (s == 6) asm volatile("cp.async.wait_group 1;");
            else             asm volatile("cp.async.wait_group 0;");
            // cross-warp visibility of cp.async within the producer group:
            // each warp waited for its own copies; barrier publishes them to the
            // other producer warp before the cvt reads rows it didn't copy.
            BAR_SYNC_PROD();

            // cvt A32[r] -> A16[r]: rows ptid and ptid+64 (32 floats each)
            const char* a32 = smc + A32_OFF + r * A32_STAGE;
            char*       a16 = smc + A16_OFF + r * A16_STAGE;
            #pragma unroll
            for (int rr = 0; rr < 2; ++rr) {
                const int m = ptid + rr * 64;
                float4 v[8];
                #pragma unroll
                for (int j = 0; j < 8; ++j)
                    v[j] = *reinterpret_cast<const float4*>(
                        a32 + m * 128 + ((j ^ (m & 7)) << 4));
                #pragma unroll
                for (int c = 0; c < 4; ++c) {
                    uint4 u;
                    u.x = h2u(__floats2half2_rn(v[2*c].x,   v[2*c].y));
                    u.y = h2u(__floats2half2_rn(v[2*c].z,   v[2*c].w));
                    u.z = h2u(__floats2half2_rn(v[2*c+1].x, v[2*c+1].y));
                    u.w = h2u(__floats2half2_rn(v[2*c+1].z, v[2*c+1].w));
                    *reinterpret_cast<uint4*>(a16 + m * 80 + c * 16) = u;
                }
            }
            BAR_SYNC(1 + r);   // publish stage r (cp.async rule: wait_group + bar.sync)
        }
        return;
    }

    // ================= consumers =================
    const int grp = lane >> 2;       // 0..7
    const int qc  = lane & 3;        // 0..3
    const int wm  = wid >> 2;        // 0..1
    const int wn  = wid & 3;         // 0..3

    const int aRow = wm * 64 + ((lane >> 3) & 1) * 8 + (lane & 7);
    const uint32_t aOffL = (uint32_t)(aRow * 80 + (lane >> 4) * 16);
    const int bRow = wn * 32 + (lane >> 4) * 8 + (lane & 7);
    const uint32_t bOffL = (uint32_t)(bRow * 80 + ((lane >> 3) & 1) * 16);

    float acc[4][4][4];
    #pragma unroll
    for (int i = 0; i < 4; i++)
        #pragma unroll
        for (int j = 0; j < 4; j++)
            #pragma unroll
            for (int q = 0; q < 4; q++)
                acc[i][j][q] = 0.0f;

    #pragma unroll 1
    for (int s = 0; s < NSLICE; ++s) {
        const int r = s % 3;
        BAR_SYNC(1 + r);                                 // wait stage r full

        const uint32_t aBase = sb + A16_OFF + (uint32_t)r * A16_STAGE + aOffL;
        const uint32_t bBase = sb + B16_OFF + (uint32_t)r * B16_STAGE + bOffL;

        #pragma unroll
        for (int ks = 0; ks < 2; ++ks) {
            uint32_t b0[4], b1[4];
            ldmx4(b0, bBase + ks * 32);
            ldmx4(b1, bBase + 16 * 80 + ks * 32);
            #pragma unroll
            for (int mb = 0; mb < 4; ++mb) {
                uint32_t a[4];
                ldmx4(a, aBase + mb * (16 * 80) + ks * 32);
                mma_f16(acc[mb][0], a, b0);
                mma_f16(acc[mb][1], a, b0 + 2);
                mma_f16(acc[mb][2], a, b1);
                mma_f16(acc[mb][3], a, b1 + 2);
            }
        }
        BAR_ARRIVE(4 + r);                               // stage r free
    }

    // ---------------- epilogue: tanh + permuted scatter ----------------
    #pragma unroll
    for (int mb = 0; mb < 4; ++mb) {
        int mrow = mt * 128 + wm * 64 + mb * 16 + grp;
        int ra = g_inv[kz * NPER + mrow];
        int rb = g_inv[kz * NPER + mrow + 8];
        #pragma unroll
        for (int nb = 0; nb < 4; ++nb) {
            int col = half * 128 + wn * 32 + nb * 8 + 2 * qc;
            float2 v0, v1;
            v0.x = fast_tanh(acc[mb][nb][0]);
            v0.y = fast_tanh(acc[mb][nb][1]);
            v1.x = fast_tanh(acc[mb][nb][2]);
            v1.y = fast_tanh(acc[mb][nb][3]);
            *reinterpret_cast<float2*>(out + (size_t)ra * DD + col) = v0;
            *reinterpret_cast<float2*>(out + (size_t)rb * DD + col) = v1;
        }
    }
}

// ---------------------------------------------------------------- launch
extern "C" void kernel_launch(void* const* d_in, const int* in_sizes, int n_in,
                              void* d_out, int out_size)
{
    const float* x    = (const float*)d_in[0];
    const float* w    = (const float*)d_in[1];
    const int*   perm = (const int*)d_in[2];
    float*       out  = (float*)d_out;

    cudaFuncSetAttribute(gemm_ws_f16,
                         cudaFuncAttributeMaxDynamicSharedMemorySize, SMEM_BYTES);

    prep_kernel<<<(KT * DD * DD + 255) / 256, 256>>>(perm, w);

    dim3 grid(2, 128, 16);
    gemm_ws_f16<<<grid, 320, SMEM_BYTES>>>(x, out);
}